// round 3
// baseline (speedup 1.0000x reference)
#include <cuda_runtime.h>
#include <math.h>

#define BB 4
#define TT 4096
#define DD 32
#define SPLITS 8
#define CHUNK 512      // TT / SPLITS
#define MTILE 128      // query rows per CTA (2 per thread)
#define NKEY 64        // key rows per smem tile

typedef unsigned long long u64;

// Scratch (no cudaMalloc allowed)
__device__ float g_q[BB * TT * DD];
__device__ float g_k[BB * TT * DD];
__device__ float g_v[BB * TT * DD];
__device__ float g_po[BB * SPLITS * TT * DD];   // partial o (unnormalized)
__device__ float g_pml[BB * SPLITS * TT * 2];   // partial (m, l)

// ---- packed f32x2 helpers (Blackwell 2x-rate fp32 path; ptxas won't emit from C++) ----
__device__ __forceinline__ u64 ffma2(u64 a, u64 b, u64 c) {
    u64 d; asm("fma.rn.f32x2 %0, %1, %2, %3;" : "=l"(d) : "l"(a), "l"(b), "l"(c)); return d;
}
__device__ __forceinline__ u64 fmul2(u64 a, u64 b) {
    u64 d; asm("mul.rn.f32x2 %0, %1, %2;" : "=l"(d) : "l"(a), "l"(b)); return d;
}
__device__ __forceinline__ u64 fadd2(u64 a, u64 b) {
    u64 d; asm("add.rn.f32x2 %0, %1, %2;" : "=l"(d) : "l"(a), "l"(b)); return d;
}
__device__ __forceinline__ u64 pack2(float lo, float hi) {
    u64 d; asm("mov.b64 %0, {%1, %2};" : "=l"(d) : "f"(lo), "f"(hi)); return d;
}
__device__ __forceinline__ float2 unpack2(u64 a) {
    float2 r; asm("mov.b64 {%0, %1}, %2;" : "=f"(r.x), "=f"(r.y) : "l"(a)); return r;
}

// ---------------------------------------------------------------------------
// Kernel 1: QKV projection. W rows live in registers (thread -> h = lane),
// x staged in smem, broadcast-read. 128 threads = 4 warps, 128 rows / block.
// ---------------------------------------------------------------------------
__global__ void __launch_bounds__(128) qkv_kernel(const float* __restrict__ x,
                                                  const float* __restrict__ Wq,
                                                  const float* __restrict__ Wk,
                                                  const float* __restrict__ Wv) {
    __shared__ float4 xs[128 * 8];   // 128 rows x 32 floats = 16KB
    const int tid = threadIdx.x, lane = tid & 31, warp = tid >> 5;

    float wq[32], wk[32], wv[32];
    {
        const float4* Wq4 = (const float4*)(Wq + lane * DD);
        const float4* Wk4 = (const float4*)(Wk + lane * DD);
        const float4* Wv4 = (const float4*)(Wv + lane * DD);
#pragma unroll
        for (int j = 0; j < 8; j++) {
            ((float4*)wq)[j] = Wq4[j];
            ((float4*)wk)[j] = Wk4[j];
            ((float4*)wv)[j] = Wv4[j];
        }
    }
    const int rowbase = blockIdx.x * 128;
    const float4* xg = (const float4*)(x + rowbase * DD);
    for (int idx = tid; idx < 128 * 8; idx += 128) xs[idx] = xg[idx];
    __syncthreads();

#pragma unroll 4
    for (int rr = 0; rr < 32; rr++) {
        const int row = warp * 32 + rr;
        float aq = 0.f, ak = 0.f, av = 0.f;
#pragma unroll
        for (int j = 0; j < 8; j++) {
            float4 xv = xs[row * 8 + j];
            aq = fmaf(xv.x, wq[4*j],   aq); ak = fmaf(xv.x, wk[4*j],   ak); av = fmaf(xv.x, wv[4*j],   av);
            aq = fmaf(xv.y, wq[4*j+1], aq); ak = fmaf(xv.y, wk[4*j+1], ak); av = fmaf(xv.y, wv[4*j+1], av);
            aq = fmaf(xv.z, wq[4*j+2], aq); ak = fmaf(xv.z, wk[4*j+2], ak); av = fmaf(xv.z, wv[4*j+2], av);
            aq = fmaf(xv.w, wq[4*j+3], aq); ak = fmaf(xv.w, wk[4*j+3], ak); av = fmaf(xv.w, wv[4*j+3], av);
        }
        const int g = (rowbase + row) * DD + lane;
        g_q[g] = aq; g_k[g] = ak; g_v[g] = av;
    }
}

// ---------------------------------------------------------------------------
// Kernel 2: partial flash attention, split-KV, packed f32x2 math.
// grid = (TT/128, SPLITS, BB); 64 threads; thread -> rows (2*tid, 2*tid+1).
// ---------------------------------------------------------------------------
__global__ void __launch_bounds__(64) attn_partial_kernel() {
    const int i  = blockIdx.x;   // 128-row query tile
    const int sp = blockIdx.y;   // kv split
    const int b  = blockIdx.z;
    if (sp * 4 > i) return;      // chunk entirely above the diagonal

    const int tid = threadIdx.x;
    const int r0 = i * MTILE + 2 * tid;
    const int r1 = r0 + 1;

    __shared__ ulonglong2 Ks[NKEY * 8];   // 64 rows x 128B
    __shared__ ulonglong2 Vs[NKEY * 8];

    const u64 SC2 = pack2(0.17677669529663687f, 0.17677669529663687f);  // 32^-0.5
    u64 q[2][16], o[2][16];
    {
        const ulonglong2* qg = (const ulonglong2*)(g_q + (b * TT + r0) * DD);
#pragma unroll
        for (int j = 0; j < 8; j++) {
            ulonglong2 t = qg[j];
            q[0][2*j] = fmul2(t.x, SC2); q[0][2*j+1] = fmul2(t.y, SC2);
        }
#pragma unroll
        for (int j = 0; j < 8; j++) {
            ulonglong2 t = qg[8 + j];
            q[1][2*j] = fmul2(t.x, SC2); q[1][2*j+1] = fmul2(t.y, SC2);
        }
#pragma unroll
        for (int j = 0; j < 16; j++) { o[0][j] = 0ull; o[1][j] = 0ull; }
    }
    float m0 = -INFINITY, l0 = 0.f, m1 = -INFINITY, l1 = 0.f;

    const int nkt = min(CHUNK / NKEY, 2 * i + 2 - 8 * sp);  // causal key tiles
    const ulonglong2* Kg = (const ulonglong2*)(g_k + (b * TT + sp * CHUNK) * DD);
    const ulonglong2* Vg = (const ulonglong2*)(g_v + (b * TT + sp * CHUNK) * DD);

    for (int jt = 0; jt < nkt; jt++) {
        if (jt) __syncthreads();
#pragma unroll
        for (int u = 0; u < 8; u++) {
            Ks[tid + 64 * u] = Kg[jt * 512 + tid + 64 * u];
            Vs[tid + 64 * u] = Vg[jt * 512 + tid + 64 * u];
        }
        __syncthreads();

        const int ktbase = sp * CHUNK + jt * NKEY;
        const int lim = min(NKEY, r1 - ktbase + 1);
        for (int n = 0; n < lim; n++) {
            ulonglong2 kk[8];
#pragma unroll
            for (int j = 0; j < 8; j++) kk[j] = Ks[n * 8 + j];

            u64 a00 = 0ull, a01 = 0ull, a10 = 0ull, a11 = 0ull;
#pragma unroll
            for (int j = 0; j < 8; j++) {
                a00 = ffma2(q[0][2*j],   kk[j].x, a00);
                a01 = ffma2(q[0][2*j+1], kk[j].y, a01);
                a10 = ffma2(q[1][2*j],   kk[j].x, a10);
                a11 = ffma2(q[1][2*j+1], kk[j].y, a11);
            }
            float2 s0 = unpack2(fadd2(a00, a01));
            float2 s1 = unpack2(fadd2(a10, a11));
            const float sc0 = s0.x + s0.y;
            const float sc1 = s1.x + s1.y;

            ulonglong2 vv[8];
#pragma unroll
            for (int j = 0; j < 8; j++) vv[j] = Vs[n * 8 + j];

            const int kt = ktbase + n;
            // Reference quirk: tril(wei)==0 -> -inf. Causal + exact-zero check.
            if (kt <= r0 && sc0 != 0.0f) {
                if (sc0 > m0) {
                    float c = __expf(m0 - sc0); m0 = sc0; l0 *= c;
                    u64 c2 = pack2(c, c);
#pragma unroll
                    for (int j = 0; j < 16; j++) o[0][j] = fmul2(o[0][j], c2);
                }
                float p = __expf(sc0 - m0); l0 += p;
                u64 p2 = pack2(p, p);
#pragma unroll
                for (int j = 0; j < 8; j++) {
                    o[0][2*j]   = ffma2(p2, vv[j].x, o[0][2*j]);
                    o[0][2*j+1] = ffma2(p2, vv[j].y, o[0][2*j+1]);
                }
            }
            if (sc1 != 0.0f) {   // kt <= r1 guaranteed by lim
                if (sc1 > m1) {
                    float c = __expf(m1 - sc1); m1 = sc1; l1 *= c;
                    u64 c2 = pack2(c, c);
#pragma unroll
                    for (int j = 0; j < 16; j++) o[1][j] = fmul2(o[1][j], c2);
                }
                float p = __expf(sc1 - m1); l1 += p;
                u64 p2 = pack2(p, p);
#pragma unroll
                for (int j = 0; j < 8; j++) {
                    o[1][2*j]   = ffma2(p2, vv[j].x, o[1][2*j]);
                    o[1][2*j+1] = ffma2(p2, vv[j].y, o[1][2*j+1]);
                }
            }
        }
    }

    const int base = (b * SPLITS + sp) * TT;
    g_pml[2*(base + r0)]     = m0;
    g_pml[2*(base + r0) + 1] = l0;
    g_pml[2*(base + r1)]     = m1;
    g_pml[2*(base + r1) + 1] = l1;
    ulonglong2* po0 = (ulonglong2*)(g_po + (base + r0) * DD);
    ulonglong2* po1 = (ulonglong2*)(g_po + (base + r1) * DD);
#pragma unroll
    for (int j = 0; j < 8; j++) po0[j] = make_ulonglong2(o[0][2*j], o[0][2*j+1]);
#pragma unroll
    for (int j = 0; j < 8; j++) po1[j] = make_ulonglong2(o[1][2*j], o[1][2*j+1]);
}

// ---------------------------------------------------------------------------
// Kernel 3: combine partial states across splits.
// ---------------------------------------------------------------------------
__global__ void __launch_bounds__(128) attn_combine_kernel(float* __restrict__ out) {
    const int tid = threadIdx.x;
    const int warp = tid >> 5, lane = tid & 31;
    const int row = blockIdx.x * 4 + warp;      // 0 .. BB*TT-1
    const int b = row / TT, t = row % TT;
    const int nS = t / CHUNK + 1;

    float M = -INFINITY, L = 0.f, acc = 0.f;
    const float2* pml2 = (const float2*)g_pml;
#pragma unroll 4
    for (int s2 = 0; s2 < nS; s2++) {
        const int pidx = (b * SPLITS + s2) * TT + t;
        float2 ml = pml2[pidx];
        if (ml.y == 0.0f) continue;            // split contributed nothing
        float os = g_po[pidx * DD + lane];
        if (ml.x > M) {
            float c = __expf(M - ml.x);
            L *= c; acc *= c; M = ml.x;
        }
        float w = __expf(ml.x - M);
        L   = fmaf(w, ml.y, L);
        acc = fmaf(w, os, acc);
    }
    out[row * DD + lane] = acc / L;
}

// ---------------------------------------------------------------------------
extern "C" void kernel_launch(void* const* d_in, const int* in_sizes, int n_in,
                              void* d_out, int out_size) {
    const float* x  = (const float*)d_in[0];
    const float* Wq = (const float*)d_in[1];
    const float* Wk = (const float*)d_in[2];
    const float* Wv = (const float*)d_in[3];
    float* out = (float*)d_out;

    qkv_kernel<<<(BB * TT) / 128, 128>>>(x, Wq, Wk, Wv);

    dim3 grid(TT / MTILE, SPLITS, BB);
    attn_partial_kernel<<<grid, 64>>>();

    attn_combine_kernel<<<(BB * TT) / 4, 128>>>(out);
}